// round 6
// baseline (speedup 1.0000x reference)
#include <cuda_runtime.h>
#include <cuda_bf16.h>
#include <math.h>
#include <cstdint>

// Problem constants
#define Bz   128
#define Kz   128
#define Dz   512
#define Lz   2
#define DIz  1024
#define Mz   (Bz*Kz)        // 16384 rows
#define HWz  4096

// GEMM tiling: CTA 256 threads, tile 256x128, 8 warps of 64x64 (4m x 2n), BK=32
#define BM 256
#define BN 128
#define BK 32
#define ASTR 36
#define BSTR 136
#define A_TILE_F (BM*ASTR)                      // 9216
#define B_TILE_F (BK*BSTR)                      // 4352
#define STAGE_F  (A_TILE_F + B_TILE_F)          // 13568
#define NSTAGE 3
#define DSMEM_BYTES (NSTAGE*STAGE_F*4)          // 162816 B

// ---------------- scratch globals -------------------------------------------
__device__ float g_x   [Mz*Dz];
__device__ float g_lnf [Mz*Dz];
__device__ float g_h   [Mz*2048];       // GLU out / ffn1 out
__device__ float g_res [Mz*Dz];
__device__ float g_enc [Mz*256];
__device__ float g_cent[Mz*2];
// precomputed weights/biases
__device__ float g_wcat[2*512*4096];    // folded+permuted in-proj (z/gate interleaved)
__device__ float g_bcat[2*4096];
__device__ float g_wmid[2*2560*512];    // [WfoMt ; WboMb ; Mt+Mb]
__device__ float g_bmid[2*512];
__device__ float g_wf1 [2*512*2048];    // folded ffn1
__device__ float g_bf1 [2*2048];
__device__ float g_zero[512];           // zero bias (static zero-init)

// ---------------- helpers ---------------------------------------------------
__device__ __forceinline__ uint32_t smem_u32(const void* p){
  uint32_t a;
  asm("{ .reg .u64 t; cvta.to.shared.u64 t, %1; cvt.u32.u64 %0, t; }" : "=r"(a) : "l"(p));
  return a;
}
__device__ __forceinline__ void cpa16(void* dst, const void* src){
  asm volatile("cp.async.cg.shared.global [%0], [%1], 16;"
               :: "r"(smem_u32(dst)), "l"(src) : "memory");
}
__device__ __forceinline__ void cpa_commit(){
  asm volatile("cp.async.commit_group;" ::: "memory");
}
template<int N> __device__ __forceinline__ void cpa_wait(){
  asm volatile("cp.async.wait_group %0;" :: "n"(N) : "memory");
}
__device__ __forceinline__ void mma_tf32(float* d, const uint32_t* a, const uint32_t* b){
  asm volatile(
    "mma.sync.aligned.m16n8k8.row.col.f32.tf32.tf32.f32 "
    "{%0,%1,%2,%3}, {%4,%5,%6,%7}, {%8,%9}, {%0,%1,%2,%3};"
    : "+f"(d[0]), "+f"(d[1]), "+f"(d[2]), "+f"(d[3])
    : "r"(a[0]), "r"(a[1]), "r"(a[2]), "r"(a[3]), "r"(b[0]), "r"(b[1]));
}
__device__ __forceinline__ float tf32rna(float x){
  float r; asm("cvt.rna.tf32.f32 %0, %1;" : "=f"(r) : "f"(x)); return r;
}
__device__ __forceinline__ float gelu_exact(float x){
  return 0.5f * x * (1.0f + erff(x * 0.70710678118654752f));
}
__device__ __forceinline__ float sigmoidf(float x){
  return 1.0f / (1.0f + expf(-x));
}

// ---------------- tf32 mma GEMM: Out = act(Acat @ W + bias) [+Add][*mask] ----
// Acat = [A1 (K1 cols) | A2 (Ktot-K1 cols)], row-major with strides ld1/ld2.
// ACT: 0 none, 1 gelu, 2 GLU (silu(even)*sigmoid(odd) -> col ((n&2047)>>1)+(n>>11)*1024)
template<int ACT, bool HAS_ADD, bool HAS_MASK>
__global__ __launch_bounds__(256, 1) void gemm2(
    const float* __restrict__ A1, int ld1, int K1,
    const float* __restrict__ A2, int ld2, int Ktot,
    const float* __restrict__ W, int N,
    const float* __restrict__ bias,
    const float* __restrict__ Add, int ldadd,
    const float* __restrict__ mask,
    float* __restrict__ Out, int ldout)
{
  extern __shared__ float sm[];
  const int tid  = threadIdx.x;
  const int lane = tid & 31;
  const int warp = tid >> 5;          // 0..7
  const int wm   = warp & 3;          // 64-row quarter
  const int wn   = warp >> 2;         // 64-col half
  const int m0 = blockIdx.y * BM;
  const int n0 = blockIdx.x * BN;

  float acc[4][8][4];
#pragma unroll
  for (int i=0;i<4;i++)
#pragma unroll
    for (int j=0;j<8;j++)
#pragma unroll
      for (int r=0;r<4;r++) acc[i][j][r]=0.f;

  const int nch = Ktot / BK;

  auto load_chunk = [&](int c){
    const int k0 = c*BK;
    const float* src; int ld;
    if (k0 < K1){ src = A1 + (size_t)m0*ld1 + k0; ld = ld1; }
    else        { src = A2 + (size_t)m0*ld2 + (k0 - K1); ld = ld2; }
    float* sA = sm + (c % NSTAGE)*STAGE_F;
    float* sB = sA + A_TILE_F;
    const float* Wb = W + (size_t)k0*N + n0;
#pragma unroll
    for (int i=0;i<8;i++){                 // A: 256 rows x 32 floats
      int idx = tid + i*256;
      int m  = idx >> 3;
      int k4 = idx & 7;
      cpa16(sA + m*ASTR + k4*4, src + (size_t)m*ld + k4*4);
    }
#pragma unroll
    for (int i=0;i<4;i++){                 // B: 32 rows x 128 floats
      int idx = tid + i*256;
      int r  = idx >> 5;
      int c4 = idx & 31;
      cpa16(sB + r*BSTR + c4*4, Wb + (size_t)r*N + c4*4);
    }
    cpa_commit();
  };

  load_chunk(0);
  if (nch > 1) load_chunk(1); else cpa_commit();

  for (int c = 0; c < nch; c++){
    if (c+2 < nch) load_chunk(c+2); else cpa_commit();
    cpa_wait<2>();
    __syncthreads();

    const float* sA = sm + (c % NSTAGE)*STAGE_F;
    const float* sB = sA + A_TILE_F;

#pragma unroll
    for (int ks = 0; ks < BK/8; ks++){
      uint32_t afr[4][4];
#pragma unroll
      for (int mi=0;mi<4;mi++){
        int r  = wm*64 + mi*16 + (lane>>2);
        int cc = ks*8 + (lane&3);
        afr[mi][0] = __float_as_uint(sA[r*ASTR + cc]);
        afr[mi][1] = __float_as_uint(sA[(r+8)*ASTR + cc]);
        afr[mi][2] = __float_as_uint(sA[r*ASTR + cc + 4]);
        afr[mi][3] = __float_as_uint(sA[(r+8)*ASTR + cc + 4]);
      }
      uint32_t bfr[8][2];
#pragma unroll
      for (int nj=0;nj<8;nj++){
        int rr = ks*8 + (lane&3);
        int cc = wn*64 + nj*8 + (lane>>2);
        bfr[nj][0] = __float_as_uint(sB[rr*BSTR + cc]);
        bfr[nj][1] = __float_as_uint(sB[(rr+4)*BSTR + cc]);
      }
#pragma unroll
      for (int mi=0;mi<4;mi++)
#pragma unroll
        for (int nj=0;nj<8;nj++)
          mma_tf32(acc[mi][nj], afr[mi], bfr[nj]);
    }
    __syncthreads();
  }

  // ---- epilogue ----
#pragma unroll
  for (int mi=0;mi<4;mi++){
    const int r0 = m0 + wm*64 + mi*16 + (lane>>2);
    const int r1 = r0 + 8;
    const float mk0 = HAS_MASK ? mask[r0] : 1.f;
    const float mk1 = HAS_MASK ? mask[r1] : 1.f;
#pragma unroll
    for (int nj=0;nj<8;nj++){
      const int cb = n0 + wn*64 + nj*8 + (lane&3)*2;
      const float b0 = bias[cb], b1 = bias[cb+1];
      float v0 = acc[mi][nj][0] + b0;
      float v1 = acc[mi][nj][1] + b1;
      float v2 = acc[mi][nj][2] + b0;
      float v3 = acc[mi][nj][3] + b1;
      if (ACT == 2){
        const int oc = ((cb & 2047) >> 1) + (cb >> 11)*1024;
        Out[(size_t)r0*ldout + oc] = v0 * sigmoidf(v0) * sigmoidf(v1);
        Out[(size_t)r1*ldout + oc] = v2 * sigmoidf(v2) * sigmoidf(v3);
      } else {
        if (ACT == 1){
          v0 = gelu_exact(v0); v1 = gelu_exact(v1);
          v2 = gelu_exact(v2); v3 = gelu_exact(v3);
        }
        if (HAS_ADD){
          v0 += Add[(size_t)r0*ldadd + cb];   v1 += Add[(size_t)r0*ldadd + cb+1];
          v2 += Add[(size_t)r1*ldadd + cb];   v3 += Add[(size_t)r1*ldadd + cb+1];
        }
        if (HAS_MASK){ v0*=mk0; v1*=mk0; v2*=mk1; v3*=mk1; }
        *(float2*)&Out[(size_t)r0*ldout + cb] = make_float2(v0, v1);
        *(float2*)&Out[(size_t)r1*ldout + cb] = make_float2(v2, v3);
      }
    }
  }
}

// ---------------- LayerNorm kernels (D=512) ---------------------------------
__device__ __forceinline__ float block_sum_128(float v, volatile float* sh){
#pragma unroll
  for (int o=16;o>0;o>>=1) v += __shfl_xor_sync(0xffffffffu, v, o);
  int w = threadIdx.x >> 5;
  if ((threadIdx.x & 31)==0) sh[w] = v;
  __syncthreads();
  float r = sh[0]+sh[1]+sh[2]+sh[3];
  __syncthreads();
  return r;
}

__global__ __launch_bounds__(128) void ln_plain_kernel(
  const float* __restrict__ X, float* __restrict__ Y)
{
  __shared__ float sh[4];
  int row = blockIdx.x, t = threadIdx.x;
  float4 v = ((const float4*)(X + (size_t)row*Dz))[t];
  float s = block_sum_128(v.x+v.y+v.z+v.w, sh);
  float mean = s * (1.0f/Dz);
  float dx=v.x-mean, dy=v.y-mean, dz=v.z-mean, dw=v.w-mean;
  float sq = block_sum_128(dx*dx+dy*dy+dz*dz+dw*dw, sh);
  float inv = rsqrtf(sq*(1.0f/Dz) + 1e-5f);
  ((float4*)(Y + (size_t)row*Dz))[t] = make_float4(dx*inv, dy*inv, dz*inv, dw*inv);
}

__global__ __launch_bounds__(128) void ln_chain2_kernel(
  const float* __restrict__ X,
  const float* __restrict__ g, const float* __restrict__ b,
  float* __restrict__ Y1, float* __restrict__ Y2)
{
  __shared__ float sh[4];
  int row = blockIdx.x, t = threadIdx.x;
  float4 v = ((const float4*)(X + (size_t)row*Dz))[t];
  float s = block_sum_128(v.x+v.y+v.z+v.w, sh);
  float mean = s * (1.0f/Dz);
  float dx=v.x-mean, dy=v.y-mean, dz=v.z-mean, dw=v.w-mean;
  float sq = block_sum_128(dx*dx+dy*dy+dz*dz+dw*dw, sh);
  float inv = rsqrtf(sq*(1.0f/Dz) + 1e-5f);
  float4 G = ((const float4*)g)[t]; float4 Bb = ((const float4*)b)[t];
  float4 y = make_float4(dx*inv*G.x+Bb.x, dy*inv*G.y+Bb.y, dz*inv*G.z+Bb.z, dw*inv*G.w+Bb.w);
  ((float4*)(Y1 + (size_t)row*Dz))[t] = y;
  float s2 = block_sum_128(y.x+y.y+y.z+y.w, sh);
  float m2 = s2 * (1.0f/Dz);
  float ex=y.x-m2, ey=y.y-m2, ez=y.z-m2, ew=y.w-m2;
  float sq2 = block_sum_128(ex*ex+ey*ey+ez*ez+ew*ew, sh);
  float inv2 = rsqrtf(sq2*(1.0f/Dz) + 1e-5f);
  ((float4*)(Y2 + (size_t)row*Dz))[t] = make_float4(ex*inv2, ey*inv2, ez*inv2, ew*inv2);
}

// ---------------- centroids / enc -------------------------------------------
__global__ __launch_bounds__(256) void centroid_kernel(
  const float* __restrict__ attn, float* __restrict__ cent, float* __restrict__ cent_out)
{
  int bk = blockIdx.x;
  const float* a = attn + (size_t)bk*HWz;
  float s=0.f, sx=0.f, sy=0.f;
#pragma unroll 4
  for (int i=threadIdx.x; i<HWz; i+=256){
    float v = a[i];
    s  += v;
    sx += v * (float)(i & 63);
    sy += v * (float)(i >> 6);
  }
#pragma unroll
  for (int o=16;o>0;o>>=1){
    s  += __shfl_xor_sync(0xffffffffu, s,  o);
    sx += __shfl_xor_sync(0xffffffffu, sx, o);
    sy += __shfl_xor_sync(0xffffffffu, sy, o);
  }
  __shared__ float sh[24];
  int w = threadIdx.x >> 5;
  if ((threadIdx.x & 31)==0){ sh[w]=s; sh[8+w]=sx; sh[16+w]=sy; }
  __syncthreads();
  if (threadIdx.x==0){
    float S=0.f, SX=0.f, SY=0.f;
    for (int i=0;i<8;i++){ S+=sh[i]; SX+=sh[8+i]; SY+=sh[16+i]; }
    float invs = 1.0f/(S + 1e-8f);
    float cx = SX * (1.0f/63.0f) * invs;
    float cy = SY * (1.0f/63.0f) * invs;
    cent[bk*2]   = cx;
    cent[bk*2+1] = cy;
    if (cent_out){ cent_out[bk*2] = cx; cent_out[bk*2+1] = cy; }
  }
}

__global__ __launch_bounds__(256) void enc_kernel(
  const float* __restrict__ cent, float* __restrict__ E)
{
  int row = blockIdx.x, j = threadIdx.x;
  int f  = j >> 6;
  int jj = j & 63;
  int fi = jj & 31;
  float feat;
  if      (f==0) feat = cent[row*2];
  else if (f==1) feat = cent[row*2+1];
  else           feat = 0.1f;
  float freq = expf(-(float)fi * 0.28782313662425575f);
  float ang = feat * freq * 3.14159f;
  E[(size_t)row*256 + j] = (jj < 32) ? sinf(ang) : cosf(ang);
}

// ---------------- weight precompute kernels ---------------------------------
__global__ __launch_bounds__(256) void build_wcat(
  const float* __restrict__ fw, const float* __restrict__ bw,
  const float* __restrict__ fg, const float* __restrict__ bg)
{
  size_t idx = (size_t)blockIdx.x*256 + threadIdx.x;   // 2*512*4096
  int n = idx & 4095;
  int k = (idx >> 12) & 511;
  int i = (int)(idx >> 21);
  int br = n >> 11;
  int j2 = n & 2047;
  int src = (j2 & 1) ? 1024 + (j2 >> 1) : (j2 >> 1);
  const float* W = (br ? bw : fw) + (size_t)i*512*2048;
  const float* G = (br ? bg : fg) + i*512;
  g_wcat[idx] = tf32rna(G[k] * W[(size_t)k*2048 + src]);
}

// bias_cat: thread-per-n coalesced dot over K=512
__global__ __launch_bounds__(128) void bias_cat(
  const float* __restrict__ fw, const float* __restrict__ bw,
  const float* __restrict__ fb, const float* __restrict__ bb,
  const float* __restrict__ fib, const float* __restrict__ bib)
{
  int i = blockIdx.y;
  int n = blockIdx.x*128 + threadIdx.x;     // 0..4095
  int br = n >> 11;
  int j2 = n & 2047;
  int src = (j2 & 1) ? 1024 + (j2 >> 1) : (j2 >> 1);
  const float* W   = (br ? bw : fw) + (size_t)i*512*2048 + src;
  const float* LNB = (br ? bb : fb) + i*512;
  const float* INB = (br ? bib : fib) + i*2048;
  float p = 0.f;
#pragma unroll 8
  for (int k = 0; k < 512; k++) p += LNB[k] * W[(size_t)k*2048];
  g_bcat[i*4096 + n] = p + INB[src];
}

__global__ __launch_bounds__(256) void build_wf1(
  const float* __restrict__ w1, const float* __restrict__ g)
{
  size_t idx = (size_t)blockIdx.x*256 + threadIdx.x;   // 2*512*2048
  int k = (int)((idx >> 11) & 511);
  int i = (int)(idx >> 20);
  g_wf1[idx] = tf32rna(g[i*512 + k] * w1[idx]);
}

__global__ __launch_bounds__(128) void bias_f1(
  const float* __restrict__ w1, const float* __restrict__ lnb,
  const float* __restrict__ b1)
{
  int i = blockIdx.y;
  int n = blockIdx.x*128 + threadIdx.x;     // 0..2047
  const float* W = w1 + (size_t)i*512*2048 + n;
  float p = 0.f;
#pragma unroll 8
  for (int k = 0; k < 512; k++) p += lnb[i*512 + k] * W[(size_t)k*2048];
  g_bf1[i*2048 + n] = p + b1[i*2048 + n];
}

__global__ __launch_bounds__(256) void build_wmid_sum(const float* __restrict__ mw)
{
  size_t idx = (size_t)blockIdx.x*256 + threadIdx.x;   // 2*512*512
  int c = idx & 511;
  int k = (int)((idx >> 9) & 511);
  int i = (int)(idx >> 18);
  const float* Mt = mw + (size_t)i*1024*512;
  g_wmid[(size_t)i*2560*512 + (size_t)(2048 + k)*512 + c] =
      tf32rna(Mt[(size_t)k*512 + c] + Mt[(size_t)(512 + k)*512 + c]);
}

__global__ __launch_bounds__(128) void bias_mid(
  const float* __restrict__ mw, const float* __restrict__ mb,
  const float* __restrict__ fob, const float* __restrict__ bob)
{
  int i = blockIdx.y;
  int c = blockIdx.x*128 + threadIdx.x;     // 0..511
  const float* Mt = mw + (size_t)i*1024*512 + c;
  float p = 0.f;
#pragma unroll 8
  for (int k = 0; k < 512; k++){
    p += fob[i*512 + k] * Mt[(size_t)k*512];
    p += bob[i*512 + k] * Mt[(size_t)(512 + k)*512];
  }
  g_bmid[i*512 + c] = p + mb[i*512 + c];
}

// ---------------- host orchestration ----------------------------------------
extern "C" void kernel_launch(void* const* d_in, const int* in_sizes, int n_in,
                              void* d_out, int out_size)
{
  const float* slots     = (const float*)d_in[0];
  const float* keep      = (const float*)d_in[1];
  const float* attn      = (const float*)d_in[2];
  const float* pm1_w     = (const float*)d_in[5];
  const float* pm1_b     = (const float*)d_in[6];
  const float* pm2_w     = (const float*)d_in[7];
  const float* pm2_b     = (const float*)d_in[8];
  const float* fwd_ln_g  = (const float*)d_in[9];
  const float* fwd_ln_b  = (const float*)d_in[10];
  const float* fwd_in_w  = (const float*)d_in[11];
  const float* fwd_in_b  = (const float*)d_in[12];
  const float* fwd_out_w = (const float*)d_in[13];
  const float* fwd_out_b = (const float*)d_in[14];
  const float* bwd_ln_g  = (const float*)d_in[15];
  const float* bwd_ln_b  = (const float*)d_in[16];
  const float* bwd_in_w  = (const float*)d_in[17];
  const float* bwd_in_b  = (const float*)d_in[18];
  const float* bwd_out_w = (const float*)d_in[19];
  const float* bwd_out_b = (const float*)d_in[20];
  const float* merge_w   = (const float*)d_in[21];
  const float* merge_b   = (const float*)d_in[22];
  const float* norm_g    = (const float*)d_in[23];
  const float* norm_b    = (const float*)d_in[24];
  const float* ffn_ln_g  = (const float*)d_in[25];
  const float* ffn_ln_b  = (const float*)d_in[26];
  const float* ffn1_w    = (const float*)d_in[27];
  const float* ffn1_b    = (const float*)d_in[28];
  const float* ffn2_w    = (const float*)d_in[29];
  const float* ffn2_b    = (const float*)d_in[30];
  float* out = (float*)d_out;

  float *xg, *lnf, *hh, *res, *enc, *cent, *wcat, *bcat, *wmid, *bmid, *wf1, *bf1, *zb;
  cudaGetSymbolAddress((void**)&xg,   g_x);
  cudaGetSymbolAddress((void**)&lnf,  g_lnf);
  cudaGetSymbolAddress((void**)&hh,   g_h);
  cudaGetSymbolAddress((void**)&res,  g_res);
  cudaGetSymbolAddress((void**)&enc,  g_enc);
  cudaGetSymbolAddress((void**)&cent, g_cent);
  cudaGetSymbolAddress((void**)&wcat, g_wcat);
  cudaGetSymbolAddress((void**)&bcat, g_bcat);
  cudaGetSymbolAddress((void**)&wmid, g_wmid);
  cudaGetSymbolAddress((void**)&bmid, g_bmid);
  cudaGetSymbolAddress((void**)&wf1,  g_wf1);
  cudaGetSymbolAddress((void**)&bf1,  g_bf1);
  cudaGetSymbolAddress((void**)&zb,   g_zero);

  float* cent_out = nullptr;
  if ((long long)out_size >= (long long)Mz*Dz + (long long)Mz*2)
    cent_out = out + (size_t)Mz*Dz;

  cudaFuncSetAttribute(gemm2<0,false,false>, cudaFuncAttributeMaxDynamicSharedMemorySize, DSMEM_BYTES);
  cudaFuncSetAttribute(gemm2<1,false,false>, cudaFuncAttributeMaxDynamicSharedMemorySize, DSMEM_BYTES);
  cudaFuncSetAttribute(gemm2<0,true ,false>, cudaFuncAttributeMaxDynamicSharedMemorySize, DSMEM_BYTES);
  cudaFuncSetAttribute(gemm2<0,true ,true >, cudaFuncAttributeMaxDynamicSharedMemorySize, DSMEM_BYTES);
  cudaFuncSetAttribute(gemm2<2,false,false>, cudaFuncAttributeMaxDynamicSharedMemorySize, DSMEM_BYTES);

  const dim3 blk(256);

  // ---- precompute (tiny) ----
  build_wcat<<<16384, 256>>>(fwd_in_w, bwd_in_w, fwd_ln_g, bwd_ln_g);
  bias_cat<<<dim3(32,2), 128>>>(fwd_in_w, bwd_in_w, fwd_ln_b, bwd_ln_b, fwd_in_b, bwd_in_b);
  build_wf1<<<8192, 256>>>(ffn1_w, ffn_ln_g);
  bias_f1<<<dim3(16,2), 128>>>(ffn1_w, ffn_ln_b, ffn1_b);
  for (int i = 0; i < Lz; i++){
    // Wfo (1024x512) @ Mt  -> wmid rows 0..1023   (M=1024 = 4 * BM grid.y)
    gemm2<0,false,false><<<dim3(4,4), blk, DSMEM_BYTES>>>(
        fwd_out_w + (size_t)i*1024*512, 512, 512,
        fwd_out_w, 512, 512,
        merge_w + (size_t)i*1024*512, 512, zb,
        nullptr, 0, nullptr,
        wmid + (size_t)i*2560*512, 512);
    // Wbo (1024x512) @ Mb  -> wmid rows 1024..2047
    gemm2<0,false,false><<<dim3(4,4), blk, DSMEM_BYTES>>>(
        bwd_out_w + (size_t)i*1024*512, 512, 512,
        bwd_out_w, 512, 512,
        merge_w + (size_t)i*1024*512 + (size_t)512*512, 512, zb,
        nullptr, 0, nullptr,
        wmid + (size_t)i*2560*512 + (size_t)1024*512, 512);
  }
  build_wmid_sum<<<2048, 256>>>(merge_w);
  bias_mid<<<dim3(4,2), 128>>>(merge_w, merge_b, fwd_out_b, bwd_out_b);

  // ---- positional encoding path ----
  centroid_kernel<<<Mz, 256>>>(attn, cent, cent_out);
  enc_kernel<<<Mz, 256>>>(cent, enc);
  gemm2<1,false,false><<<dim3(4,64), blk, DSMEM_BYTES>>>(
      enc, 256, 256, enc, 256, 256, pm1_w, 512, pm1_b,
      nullptr, 0, nullptr, lnf, 512);
  gemm2<0,true,false><<<dim3(4,64), blk, DSMEM_BYTES>>>(
      lnf, 512, 512, lnf, 512, 512, pm2_w, 512, pm2_b,
      slots, 512, nullptr, xg, 512);

  // ---- layers ----
  for (int i = 0; i < Lz; i++){
    ln_plain_kernel<<<Mz, 128>>>(xg, lnf);
    // fused fwd+bwd in-proj with GLU epilogue
    gemm2<2,false,false><<<dim3(32,64), blk, DSMEM_BYTES>>>(
        lnf, 512, 512, lnf, 512, 512,
        wcat + (size_t)i*512*4096, 4096, bcat + (size_t)i*4096,
        nullptr, 0, nullptr, hh, 2048);
    // fused out-proj + merge + residual
    gemm2<0,true,false><<<dim3(4,64), blk, DSMEM_BYTES>>>(
        hh, 2048, 2048, xg, 512, 2560,
        wmid + (size_t)i*2560*512, 512, bmid + (size_t)i*512,
        xg, 512, nullptr, res, 512);
    ln_chain2_kernel<<<Mz, 128>>>(res, norm_g + i*Dz, norm_b + i*Dz, xg, lnf);
    // ffn1 with gelu
    gemm2<1,false,false><<<dim3(16,64), blk, DSMEM_BYTES>>>(
        lnf, 512, 512, lnf, 512, 512,
        wf1 + (size_t)i*512*2048, 2048, bf1 + (size_t)i*2048,
        nullptr, 0, nullptr, hh, 2048);
    // ffn2 + residual + mask
    float* dst = (i == Lz-1) ? out : xg;
    gemm2<0,true,true><<<dim3(4,64), blk, DSMEM_BYTES>>>(
        hh, 2048, 2048, hh, 2048, 2048,
        ffn2_w + (size_t)i*2048*512, 512, ffn2_b + (size_t)i*512,
        xg, 512, keep, dst, 512);
  }
}